// round 4
// baseline (speedup 1.0000x reference)
#include <cuda_runtime.h>

// out[i, :] = sum_k ppr_scores[i,k] * x[ppr_idx[i,k], :]
// N=100000, K=32, D=128 (fp32). One warp per output row per iteration;
// lane l holds (idx[l], score[l]) broadcast via shfl; warp reads neighbor
// rows as coalesced 512B LDG.128. x (51MB) is L2-resident; kernel rides the
// LTS data-return ceiling (~25 TB/s).
//
// R4 change: grid-stride persistent warps. R1's 12500 short CTAs cause
// launch/drain churn — each fresh warp stalls on its idx/score load before
// any gather issues, opening L2 request gaps. Persistent warps (1184 CTAs,
// ~10.6 rows each) keep the L2 queue fed and let ptxas overlap the next
// row's idx/score load with the current row's tail FMAs.

#define KNEIGH 32
#define DVEC   32   // D/4 float4 per row

__global__ __launch_bounds__(256) void ppr_gather_kernel(
    const float4* __restrict__ x,      // [N, 32] float4
    const int*    __restrict__ idx,    // [N, 32]
    const float*  __restrict__ sc,     // [N, 32]
    float4*       __restrict__ out,    // [N, 32] float4
    int n)
{
    const int lane    = threadIdx.x & 31;
    const int warp0   = (blockIdx.x * blockDim.x + threadIdx.x) >> 5;
    const int nwarps  = (gridDim.x * blockDim.x) >> 5;

    for (int row = warp0; row < n; row += nwarps) {
        // Lane-held neighbor index/score for this row (K == warpSize).
        const int   my_j = idx[row * KNEIGH + lane];
        const float my_s = sc[row * KNEIGH + lane];

        float4 acc = make_float4(0.f, 0.f, 0.f, 0.f);

        #pragma unroll
        for (int k = 0; k < KNEIGH; k += 8) {
            float4 v[8];
            float  s[8];
            #pragma unroll
            for (int u = 0; u < 8; ++u) {
                const int jk = __shfl_sync(0xffffffffu, my_j, k + u);
                s[u]         = __shfl_sync(0xffffffffu, my_s, k + u);
                v[u]         = x[(long long)jk * DVEC + lane];
            }
            #pragma unroll
            for (int u = 0; u < 8; ++u) {
                acc.x += s[u] * v[u].x;
                acc.y += s[u] * v[u].y;
                acc.z += s[u] * v[u].z;
                acc.w += s[u] * v[u].w;
            }
        }

        out[row * DVEC + lane] = acc;
    }
}

extern "C" void kernel_launch(void* const* d_in, const int* in_sizes, int n_in,
                              void* d_out, int out_size)
{
    const float4* x   = (const float4*)d_in[0];   // [N, D] fp32
    const int*    idx = (const int*)d_in[1];      // [N, K] int32
    const float*  sc  = (const float*)d_in[2];    // [N, K] fp32
    float4*       out = (float4*)d_out;           // [N, D] fp32

    const int n = in_sizes[1] / KNEIGH;           // N rows

    // Persistent shape: fill 148 SMs with 8 CTAs of 256 threads each
    // (2048 threads/SM target), grid-stride over the 100000 rows.
    const int blocks = 148 * 8;
    ppr_gather_kernel<<<blocks, 256>>>(x, idx, sc, out, n);
}

// round 5
// speedup vs baseline: 1.1317x; 1.1317x over previous
#include <cuda_runtime.h>

// out[i, :] = sum_k ppr_scores[i,k] * x[ppr_idx[i,k], :]
// N=100000, K=32, D=128 (fp32). One warp per output row; lane l holds
// (idx[l], score[l]) broadcast via shfl; warp reads neighbor rows as
// coalesced 512B LDG.128 (4 lines). x (51MB) is L2-resident; kernel rides
// the LTS data-return plateau (~83% in R1).
//
// R5: exact R1 skeleton (one-shot CTAs, 256 thr, 32-reg budget, occ ~89% —
// proven the dominant variable across R1-R4), with the load batch reduced
// 8 -> 4. Rationale: B300 cross-CTA L1tex-queue contention scales with
// oe*MLP_p1; batch-8 x nL=4 front-batched lines at occ 8 CTAs/SM creates
// completion spread and LTS request gaps. Batch-4 halves queue depth while
// ~57 warps/SM still sustain >200 outstanding loads per SM.

#define KNEIGH 32
#define DVEC   32   // D/4 float4 per row

__global__ __launch_bounds__(256) void ppr_gather_kernel(
    const float4* __restrict__ x,      // [N, 32] float4
    const int*    __restrict__ idx,    // [N, 32]
    const float*  __restrict__ sc,     // [N, 32]
    float4*       __restrict__ out,    // [N, 32] float4
    int n)
{
    const int warp = (blockIdx.x * blockDim.x + threadIdx.x) >> 5;
    const int lane = threadIdx.x & 31;
    if (warp >= n) return;

    // Lane-held neighbor index/score for this row (K == warpSize).
    const int   my_j = idx[warp * KNEIGH + lane];
    const float my_s = sc[warp * KNEIGH + lane];

    float4 acc = make_float4(0.f, 0.f, 0.f, 0.f);

    #pragma unroll
    for (int k = 0; k < KNEIGH; k += 4) {
        float4 v[4];
        float  s[4];
        #pragma unroll
        for (int u = 0; u < 4; ++u) {
            const int jk = __shfl_sync(0xffffffffu, my_j, k + u);
            s[u]         = __shfl_sync(0xffffffffu, my_s, k + u);
            v[u]         = x[(long long)jk * DVEC + lane];
        }
        #pragma unroll
        for (int u = 0; u < 4; ++u) {
            acc.x += s[u] * v[u].x;
            acc.y += s[u] * v[u].y;
            acc.z += s[u] * v[u].z;
            acc.w += s[u] * v[u].w;
        }
    }

    out[warp * DVEC + lane] = acc;
}

extern "C" void kernel_launch(void* const* d_in, const int* in_sizes, int n_in,
                              void* d_out, int out_size)
{
    const float4* x   = (const float4*)d_in[0];   // [N, D] fp32
    const int*    idx = (const int*)d_in[1];      // [N, K] int32
    const float*  sc  = (const float*)d_in[2];    // [N, K] fp32
    float4*       out = (float4*)d_out;           // [N, D] fp32

    const int n = in_sizes[1] / KNEIGH;           // N rows

    const int warps_per_block = 8;                // 256 threads
    const int blocks = (n + warps_per_block - 1) / warps_per_block;
    ppr_gather_kernel<<<blocks, warps_per_block * 32>>>(x, idx, sc, out, n);
}